// round 15
// baseline (speedup 1.0000x reference)
#include <cuda_runtime.h>
#include <cstdint>

#define S_    32
#define IN_   2048
#define OUT_  2048
#define TPB   256
#define SGRP  8                   // samples per block
#define QBLK  (S_ / SGRP)         // 4 s-quarters -> grid = OUT_ * QBLK
#define IN2   (IN_ / 2)           // float2 elements per row

// ---------------------------------------------------------------------------
// Host-side threefry2x32 (subkey derivation for jax.random.key(42) only)
// ---------------------------------------------------------------------------
static inline uint32_t h_rotl32(uint32_t x, int r) {
    return (x << r) | (x >> (32 - r));
}
static inline void h_round(uint32_t& x0, uint32_t& x1, int r) {
    x0 += x1; x1 = h_rotl32(x1, r); x1 ^= x0;
}
static void h_threefry2x32(uint32_t k0, uint32_t k1, uint32_t c0, uint32_t c1,
                           uint32_t& o0, uint32_t& o1)
{
    const uint32_t k2 = k0 ^ k1 ^ 0x1BD11BDAu;
    uint32_t x0 = c0 + k0, x1 = c1 + k1;
    h_round(x0,x1,13); h_round(x0,x1,15); h_round(x0,x1,26); h_round(x0,x1,6);
    x0 += k1; x1 += k2 + 1u;
    h_round(x0,x1,17); h_round(x0,x1,29); h_round(x0,x1,16); h_round(x0,x1,24);
    x0 += k2; x1 += k0 + 2u;
    h_round(x0,x1,13); h_round(x0,x1,15); h_round(x0,x1,26); h_round(x0,x1,6);
    x0 += k0; x1 += k1 + 3u;
    h_round(x0,x1,17); h_round(x0,x1,29); h_round(x0,x1,16); h_round(x0,x1,24);
    x0 += k1; x1 += k2 + 4u;
    h_round(x0,x1,13); h_round(x0,x1,15); h_round(x0,x1,26); h_round(x0,x1,6);
    x0 += k2; x1 += k0 + 5u;
    o0 = x0; o1 = x1;
}

// ---------------------------------------------------------------------------
// Device threefry (proven form): adds as IMAD (full-rate fma pipe, opaque
// `one`), SHF+LOP3 on the half-rate alu pipe.
// ---------------------------------------------------------------------------
struct TFKeys {
    uint32_t k0, k1, k2;
    uint32_t j1, j2, j3, j4, j5;   // k2+1, k0+2, k1+3, k2+4, k0+5
};

__device__ __forceinline__ uint32_t addi(uint32_t a, uint32_t b, uint32_t one) {
    return a * one + b;            // IMAD -> fma pipe
}
__device__ __forceinline__ void tfr(uint32_t& x0, uint32_t& x1, int r, uint32_t one) {
    x0 = addi(x0, x1, one);
    x1 = __funnelshift_l(x1, x1, r);
    x1 ^= x0;
}
__device__ __forceinline__ uint32_t threefry_from_x1(const TFKeys k, uint32_t x1, uint32_t one) {
    uint32_t x0 = k.k0;            // c0 == 0

    tfr(x0,x1,13,one); tfr(x0,x1,15,one); tfr(x0,x1,26,one); tfr(x0,x1,6,one);
    x0 = addi(x0, k.k1, one); x1 = addi(x1, k.j1, one);
    tfr(x0,x1,17,one); tfr(x0,x1,29,one); tfr(x0,x1,16,one); tfr(x0,x1,24,one);
    x0 = addi(x0, k.k2, one); x1 = addi(x1, k.j2, one);
    tfr(x0,x1,13,one); tfr(x0,x1,15,one); tfr(x0,x1,26,one); tfr(x0,x1,6,one);
    x0 = addi(x0, k.k0, one); x1 = addi(x1, k.j3, one);
    tfr(x0,x1,17,one); tfr(x0,x1,29,one); tfr(x0,x1,16,one); tfr(x0,x1,24,one);
    x0 = addi(x0, k.k1, one); x1 = addi(x1, k.j4, one);
    tfr(x0,x1,13,one); tfr(x0,x1,15,one); tfr(x0,x1,26,one); tfr(x0,x1,6,one);
    x0 = addi(x0, k.k2, one); x1 = addi(x1, k.j5, one);

    return x0 ^ x1;
}

// ---------------------------------------------------------------------------
// Tail p for eps = p*u (sqrt2-folded coeffs); l = log2(1-u^2). Cold path.
// ---------------------------------------------------------------------------
__device__ __forceinline__ float tail_p(float l) {
    float w  = __fmul_rn(l, -0.69314718f);
    float sw = __fmul_rn(w, __frsqrt_rn(w));    // sqrt(w), ~2ulp, w >= 5
    float ws = sw - 3.0f;
    float p;
    p = 8.1168911e-03f;
    p = __fmaf_rn(p, ws, -1.0779785e-02f);
    p = __fmaf_rn(p, ws, 1.3348580e-02f);
    p = __fmaf_rn(p, ws, 1.4165810e+00f);
    p = __fmaf_rn(p, ws, 4.0064341e+00f);
    return p;
}

// scalar eps for the cold bias path (own branch; not in the hot loop)
__device__ __forceinline__ float bits_to_eps_scalar(uint32_t bits) {
    float u = __fmaf_rn((float)bits, 0x1.fffffcp-32f, -0.99999994f);
    float y = __fadd_rn(1.0f, -__fmul_rn(u, u));
    float l = __log2f(y);
    float wc = __fmaf_rn(l, -0.69314718f, -2.5f);
    float p;
    p = 3.0911997e-04f;
    p = __fmaf_rn(p, wc, -1.7730364e-03f);
    p = __fmaf_rn(p, wc, -5.9081367e-03f);
    p = __fmaf_rn(p, wc, 3.4880266e-01f);
    p = __fmaf_rn(p, wc, 2.1233135e+00f);
    if (wc >= 2.5f) p = tail_p(l);
    return __fmul_rn(p, u);
}

// ---------------------------------------------------------------------------
// grid = OUT_*4: block = (output column o, s-quarter q). 8 samples per block
// in registers; float2 i-pair per thread per iteration (R12-proven layout).
// The pair's two tail checks share ONE rare branch (fmax-combined).
// counter = s*2^22 + (o*IN + i). minBlocks=6 -> 40-reg ceiling, occ ~71%
// (proven perf-equivalent to 93% for this alu-bound kernel).
// ---------------------------------------------------------------------------
__global__ void __launch_bounds__(TPB, 6)
bayes_linear_kernel(const float* __restrict__ xf,
                    const float* __restrict__ wmuf,
                    const float* __restrict__ wsigf,
                    const float* __restrict__ bmu,
                    const float* __restrict__ bsig,
                    float* __restrict__ out,
                    TFKeys wk, TFKeys bk,
                    uint32_t one, uint32_t c22 /* == 1<<22, opaque */)
{
    __shared__ float red[SGRP][(TPB / 32) + 1];   // [sample][warp] partials

    const float2* __restrict__ x2   = (const float2*)xf;
    const float2* __restrict__ wmu2 = (const float2*)wmuf;
    const float2* __restrict__ wsg2 = (const float2*)wsigf;

    const int bid   = blockIdx.x;
    const int o     = bid & (OUT_ - 1);
    const int q     = bid >> 11;                  // s-quarter
    const int sbase = q * SGRP;
    const int tid   = threadIdx.x;
    const int lane  = tid & 31;
    const int warp  = tid >> 5;
    const uint32_t base_o  = (uint32_t)o * (uint32_t)IN_;
    const int      base_o2 = o * IN2;

    float acc[SGRP];
#pragma unroll
    for (int j = 0; j < SGRP; ++j) acc[j] = 0.0f;

#pragma unroll 1
    for (int it = 0; it < IN2 / TPB; ++it) {
        const int p = it * TPB + tid;             // float2 index, i = 2p
        const float2 mu2 = wmu2[base_o2 + p];
        const float2 sg2 = wsg2[base_o2 + p];
        const float2* xp2 = x2 + (size_t)sbase * IN2 + p;

        // x1 init for j=0,d=0: sbase*2^22 + (base_o + 2p) + k1
        const uint32_t cb = addi((uint32_t)sbase,
                                 base_o + (uint32_t)(2 * p) + wk.k1, c22);

#pragma unroll
        for (int j = 0; j < SGRP; ++j) {
            const uint32_t cj = addi((uint32_t)j, cb, c22);   // cb + j*2^22
            const float2 xv = xp2[j * IN2];

            const uint32_t bits0 = threefry_from_x1(wk, cj,                one);
            const uint32_t bits1 = threefry_from_x1(wk, addi(cj, 1u, one), one);

            float u0 = __fmaf_rn((float)bits0, 0x1.fffffcp-32f, -0.99999994f);
            float u1 = __fmaf_rn((float)bits1, 0x1.fffffcp-32f, -0.99999994f);

            float y0 = __fadd_rn(1.0f, -__fmul_rn(u0, u0));
            float y1 = __fadd_rn(1.0f, -__fmul_rn(u1, u1));
            float l0 = __log2f(y0);
            float l1 = __log2f(y1);
            float wc0 = __fmaf_rn(l0, -0.69314718f, -2.5f);
            float wc1 = __fmaf_rn(l1, -0.69314718f, -2.5f);

            float p0;
            p0 = 3.0911997e-04f;
            p0 = __fmaf_rn(p0, wc0, -1.7730364e-03f);
            p0 = __fmaf_rn(p0, wc0, -5.9081367e-03f);
            p0 = __fmaf_rn(p0, wc0, 3.4880266e-01f);
            p0 = __fmaf_rn(p0, wc0, 2.1233135e+00f);

            float p1;
            p1 = 3.0911997e-04f;
            p1 = __fmaf_rn(p1, wc1, -1.7730364e-03f);
            p1 = __fmaf_rn(p1, wc1, -5.9081367e-03f);
            p1 = __fmaf_rn(p1, wc1, 3.4880266e-01f);
            p1 = __fmaf_rn(p1, wc1, 2.1233135e+00f);

            // ONE rare branch per pair (P ~0.66%): per-lane fixups inside
            if (fmaxf(wc0, wc1) >= 2.5f) {
                if (wc0 >= 2.5f) p0 = tail_p(l0);
                if (wc1 >= 2.5f) p1 = tail_p(l1);
            }

            const float eps0 = __fmul_rn(p0, u0);
            const float eps1 = __fmul_rn(p1, u1);

            acc[j] = __fmaf_rn(__fmaf_rn(sg2.x, eps0, mu2.x), xv.x, acc[j]);
            acc[j] = __fmaf_rn(__fmaf_rn(sg2.y, eps1, mu2.y), xv.y, acc[j]);
        }
    }

    // warp butterfly reduction; lane 0 stores the 8 partials
#pragma unroll
    for (int j = 0; j < SGRP; ++j) {
#pragma unroll
        for (int m = 16; m >= 1; m >>= 1)
            acc[j] += __shfl_xor_sync(0xffffffffu, acc[j], m);
    }
    if (lane == 0) {
#pragma unroll
        for (int j = 0; j < SGRP; ++j)
            red[j][warp] = acc[j];
    }

    __syncthreads();

    if (tid < SGRP) {
        float tot = 0.0f;
#pragma unroll
        for (int w = 0; w < TPB / 32; ++w) tot += red[tid][w];

        const int s = sbase + tid;
        // bias epsilon: counter = s*OUT + o over bkey (sqrt2 already folded)
        const uint32_t c1 = (uint32_t)(s * OUT_ + o);
        const float eb = bits_to_eps_scalar(threefry_from_x1(bk, c1 + bk.k1, one));
        out[s * OUT_ + o] = tot + __fmaf_rn(bsig[o], eb, bmu[o]);
    }
}

// ---------------------------------------------------------------------------
extern "C" void kernel_launch(void* const* d_in, const int* in_sizes, int n_in,
                              void* d_out, int out_size)
{
    const float* x    = (const float*)d_in[0];
    const float* wmu  = (const float*)d_in[1];
    const float* wsig = (const float*)d_in[2];
    const float* bmu  = (const float*)d_in[3];
    const float* bsig = (const float*)d_in[4];
    float* out        = (float*)d_out;

    uint32_t wk0, wk1, bk0, bk1;
    h_threefry2x32(0u, 42u, 0u, 0u, wk0, wk1);
    h_threefry2x32(0u, 42u, 0u, 1u, bk0, bk1);

    TFKeys wk, bk;
    wk.k0 = wk0; wk.k1 = wk1; wk.k2 = wk0 ^ wk1 ^ 0x1BD11BDAu;
    wk.j1 = wk.k2 + 1u; wk.j2 = wk.k0 + 2u; wk.j3 = wk.k1 + 3u;
    wk.j4 = wk.k2 + 4u; wk.j5 = wk.k0 + 5u;

    bk.k0 = bk0; bk.k1 = bk1; bk.k2 = bk0 ^ bk1 ^ 0x1BD11BDAu;
    bk.j1 = bk.k2 + 1u; bk.j2 = bk.k0 + 2u; bk.j3 = bk.k1 + 3u;
    bk.j4 = bk.k2 + 4u; bk.j5 = bk.k0 + 5u;

    bayes_linear_kernel<<<OUT_ * QBLK, TPB>>>(x, wmu, wsig, bmu, bsig, out,
                                              wk, bk, 1u, 1u << 22);
}

// round 16
// speedup vs baseline: 1.2158x; 1.2158x over previous
#include <cuda_runtime.h>
#include <cstdint>

#define S_    32
#define IN_   2048
#define OUT_  2048
#define TPB   256
#define SGRP  8                   // samples per block
#define QBLK  (S_ / SGRP)         // 4 s-quarters -> grid = OUT_ * QBLK
#define IN2   (IN_ / 2)           // float2 elements per row

// ---------------------------------------------------------------------------
// Host-side threefry2x32 (subkey derivation for jax.random.key(42) only)
// ---------------------------------------------------------------------------
static inline uint32_t h_rotl32(uint32_t x, int r) {
    return (x << r) | (x >> (32 - r));
}
static inline void h_round(uint32_t& x0, uint32_t& x1, int r) {
    x0 += x1; x1 = h_rotl32(x1, r); x1 ^= x0;
}
static void h_threefry2x32(uint32_t k0, uint32_t k1, uint32_t c0, uint32_t c1,
                           uint32_t& o0, uint32_t& o1)
{
    const uint32_t k2 = k0 ^ k1 ^ 0x1BD11BDAu;
    uint32_t x0 = c0 + k0, x1 = c1 + k1;
    h_round(x0,x1,13); h_round(x0,x1,15); h_round(x0,x1,26); h_round(x0,x1,6);
    x0 += k1; x1 += k2 + 1u;
    h_round(x0,x1,17); h_round(x0,x1,29); h_round(x0,x1,16); h_round(x0,x1,24);
    x0 += k2; x1 += k0 + 2u;
    h_round(x0,x1,13); h_round(x0,x1,15); h_round(x0,x1,26); h_round(x0,x1,6);
    x0 += k0; x1 += k1 + 3u;
    h_round(x0,x1,17); h_round(x0,x1,29); h_round(x0,x1,16); h_round(x0,x1,24);
    x0 += k1; x1 += k2 + 4u;
    h_round(x0,x1,13); h_round(x0,x1,15); h_round(x0,x1,26); h_round(x0,x1,6);
    x0 += k2; x1 += k0 + 5u;
    o0 = x0; o1 = x1;
}

// ---------------------------------------------------------------------------
// Device threefry (proven form): adds as IMAD (full-rate fma pipe, opaque
// `one`), SHF+LOP3 on the half-rate alu pipe.
// ---------------------------------------------------------------------------
struct TFKeys {
    uint32_t k0, k1, k2;
    uint32_t j1, j2, j3, j4, j5;   // k2+1, k0+2, k1+3, k2+4, k0+5
};

__device__ __forceinline__ uint32_t addi(uint32_t a, uint32_t b, uint32_t one) {
    return a * one + b;            // IMAD -> fma pipe
}
__device__ __forceinline__ void tfr(uint32_t& x0, uint32_t& x1, int r, uint32_t one) {
    x0 = addi(x0, x1, one);
    x1 = __funnelshift_l(x1, x1, r);
    x1 ^= x0;
}
__device__ __forceinline__ uint32_t threefry_from_x1(const TFKeys k, uint32_t x1, uint32_t one) {
    uint32_t x0 = k.k0;            // c0 == 0

    tfr(x0,x1,13,one); tfr(x0,x1,15,one); tfr(x0,x1,26,one); tfr(x0,x1,6,one);
    x0 = addi(x0, k.k1, one); x1 = addi(x1, k.j1, one);
    tfr(x0,x1,17,one); tfr(x0,x1,29,one); tfr(x0,x1,16,one); tfr(x0,x1,24,one);
    x0 = addi(x0, k.k2, one); x1 = addi(x1, k.j2, one);
    tfr(x0,x1,13,one); tfr(x0,x1,15,one); tfr(x0,x1,26,one); tfr(x0,x1,6,one);
    x0 = addi(x0, k.k0, one); x1 = addi(x1, k.j3, one);
    tfr(x0,x1,17,one); tfr(x0,x1,29,one); tfr(x0,x1,16,one); tfr(x0,x1,24,one);
    x0 = addi(x0, k.k1, one); x1 = addi(x1, k.j4, one);
    tfr(x0,x1,13,one); tfr(x0,x1,15,one); tfr(x0,x1,26,one); tfr(x0,x1,6,one);
    x0 = addi(x0, k.k2, one); x1 = addi(x1, k.j5, one);

    return x0 ^ x1;
}

// ---------------------------------------------------------------------------
// bits -> eps = sqrt(2)*erfinv(u), sqrt(2) folded into the coefficients.
// u via single I2F of the full word with the shrunk scale:
//   u = fma((float)bits, 0x1.fffffcp-32, -0.99999994)
// (float)bits can round UP to 2^32; the shrunk scale keeps u_max = 0.99999982
// < 1 so y = 1-u^2 stays positive. Scale distortion vs JAX <= ~2.4e-7 in u.
// Central poly: 5 coefficients (validated: rel_err 1.6e-4, 6x margin).
// Tail (P=0.33%/lane) divergent branch, 5 coeffs, sqrt via w*rsqrt(w).
// ---------------------------------------------------------------------------
__device__ __forceinline__ float bits_to_eps(uint32_t bits) {
    float v = (float)bits;                       // I2F.U32, RN
    float u = __fmaf_rn(v, 0x1.fffffcp-32f, -0.99999994f);

    float t = __fmul_rn(u, u);
    float y = __fadd_rn(1.0f, -t);
    float l = __log2f(y);
    float wc = __fmaf_rn(l, -0.69314718f, -2.5f);   // w - 2.5

    float p;
    p = 3.0911997e-04f;
    p = __fmaf_rn(p, wc, -1.7730364e-03f);
    p = __fmaf_rn(p, wc, -5.9081367e-03f);
    p = __fmaf_rn(p, wc, 3.4880266e-01f);
    p = __fmaf_rn(p, wc, 2.1233135e+00f);

    if (wc >= 2.5f) {   // rare tail: |u| > 0.99666
        float w  = __fmul_rn(l, -0.69314718f);
        float sw = __fmul_rn(w, __frsqrt_rn(w));    // sqrt(w), ~2ulp, w>=5
        float ws = sw - 3.0f;
        p = 8.1168911e-03f;
        p = __fmaf_rn(p, ws, -1.0779785e-02f);
        p = __fmaf_rn(p, ws, 1.3348580e-02f);
        p = __fmaf_rn(p, ws, 1.4165810e+00f);
        p = __fmaf_rn(p, ws, 4.0064341e+00f);
    }
    return __fmul_rn(p, u);
}

// ---------------------------------------------------------------------------
// grid = OUT_*4: block = (output column o, s-quarter q). 8 samples per block
// in registers. Each thread owns a float2 i-pair per iteration. Launch bounds
// force 8 blocks/SM (32 regs) -> full residency (regs=32 verified, no spill).
// counter = s*2^22 + (o*IN + i).
// ---------------------------------------------------------------------------
__global__ void __launch_bounds__(TPB, 8)
bayes_linear_kernel(const float* __restrict__ xf,
                    const float* __restrict__ wmuf,
                    const float* __restrict__ wsigf,
                    const float* __restrict__ bmu,
                    const float* __restrict__ bsig,
                    float* __restrict__ out,
                    TFKeys wk, TFKeys bk,
                    uint32_t one, uint32_t c22 /* == 1<<22, opaque */)
{
    __shared__ float red[SGRP][(TPB / 32) + 1];   // [sample][warp] partials

    const float2* __restrict__ x2   = (const float2*)xf;
    const float2* __restrict__ wmu2 = (const float2*)wmuf;
    const float2* __restrict__ wsg2 = (const float2*)wsigf;

    const int bid   = blockIdx.x;
    const int o     = bid & (OUT_ - 1);
    const int q     = bid >> 11;                  // s-quarter
    const int sbase = q * SGRP;
    const int tid   = threadIdx.x;
    const int lane  = tid & 31;
    const int warp  = tid >> 5;
    const uint32_t base_o  = (uint32_t)o * (uint32_t)IN_;
    const int      base_o2 = o * IN2;

    float acc[SGRP];
#pragma unroll
    for (int j = 0; j < SGRP; ++j) acc[j] = 0.0f;

#pragma unroll 1
    for (int it = 0; it < IN2 / TPB; ++it) {
        const int p = it * TPB + tid;             // float2 index, i = 2p
        const float2 mu2 = wmu2[base_o2 + p];
        const float2 sg2 = wsg2[base_o2 + p];
        const float2* xp2 = x2 + (size_t)sbase * IN2 + p;

        // x1 init for j=0,d=0: sbase*2^22 + (base_o + 2p) + k1
        const uint32_t cb = addi((uint32_t)sbase,
                                 base_o + (uint32_t)(2 * p) + wk.k1, c22);

#pragma unroll
        for (int j = 0; j < SGRP; ++j) {
            const uint32_t cj = cb + ((uint32_t)j << 22);
            const float2 xv = xp2[j * IN2];

            const uint32_t bits0 = threefry_from_x1(wk, cj,      one);
            const uint32_t bits1 = threefry_from_x1(wk, cj + 1u, one);
            const float eps0 = bits_to_eps(bits0);
            const float eps1 = bits_to_eps(bits1);

            acc[j] = __fmaf_rn(__fmaf_rn(sg2.x, eps0, mu2.x), xv.x, acc[j]);
            acc[j] = __fmaf_rn(__fmaf_rn(sg2.y, eps1, mu2.y), xv.y, acc[j]);
        }
    }

    // warp butterfly reduction; lane 0 stores the 8 partials
#pragma unroll
    for (int j = 0; j < SGRP; ++j) {
#pragma unroll
        for (int m = 16; m >= 1; m >>= 1)
            acc[j] += __shfl_xor_sync(0xffffffffu, acc[j], m);
    }
    if (lane == 0) {
#pragma unroll
        for (int j = 0; j < SGRP; ++j)
            red[j][warp] = acc[j];
    }

    __syncthreads();

    if (tid < SGRP) {
        float tot = 0.0f;
#pragma unroll
        for (int w = 0; w < TPB / 32; ++w) tot += red[tid][w];

        const int s = sbase + tid;
        // bias epsilon: counter = s*OUT + o over bkey (sqrt2 already folded)
        const uint32_t c1 = (uint32_t)(s * OUT_ + o);
        const float eb = bits_to_eps(threefry_from_x1(bk, c1 + bk.k1, one));
        out[s * OUT_ + o] = tot + __fmaf_rn(bsig[o], eb, bmu[o]);
    }
}

// ---------------------------------------------------------------------------
extern "C" void kernel_launch(void* const* d_in, const int* in_sizes, int n_in,
                              void* d_out, int out_size)
{
    const float* x    = (const float*)d_in[0];
    const float* wmu  = (const float*)d_in[1];
    const float* wsig = (const float*)d_in[2];
    const float* bmu  = (const float*)d_in[3];
    const float* bsig = (const float*)d_in[4];
    float* out        = (float*)d_out;

    uint32_t wk0, wk1, bk0, bk1;
    h_threefry2x32(0u, 42u, 0u, 0u, wk0, wk1);
    h_threefry2x32(0u, 42u, 0u, 1u, bk0, bk1);

    TFKeys wk, bk;
    wk.k0 = wk0; wk.k1 = wk1; wk.k2 = wk0 ^ wk1 ^ 0x1BD11BDAu;
    wk.j1 = wk.k2 + 1u; wk.j2 = wk.k0 + 2u; wk.j3 = wk.k1 + 3u;
    wk.j4 = wk.k2 + 4u; wk.j5 = wk.k0 + 5u;

    bk.k0 = bk0; bk.k1 = bk1; bk.k2 = bk0 ^ bk1 ^ 0x1BD11BDAu;
    bk.j1 = bk.k2 + 1u; bk.j2 = bk.k0 + 2u; bk.j3 = bk.k1 + 3u;
    bk.j4 = bk.k2 + 4u; bk.j5 = bk.k0 + 5u;

    bayes_linear_kernel<<<OUT_ * QBLK, TPB>>>(x, wmu, wsig, bmu, bsig, out,
                                              wk, bk, 1u, 1u << 22);
}